// round 17
// baseline (speedup 1.0000x reference)
#include <cuda_runtime.h>
#include <math.h>
#include <stdint.h>

// DPLSTMCell row-0, R17: R16 base (8.672us plateau) + two untested micro-levers:
//  (a) asymmetric path split: 5 rows via LDG warps / 3 rows via cp.async warps
//      (LDG is the measured-faster path: all-LDG 8.93 vs all-async ~11.0; the 4/4
//      mix left async warps finishing last).
//  (b) __ldcg (L2-only) for weight LDGs: L1 is flushed per launch so weight L1
//      allocation is pure overhead on warm replays; vectors keep default caching.
// Rows r=0..7: gate=r>>1, mat=r&1 (R1 mapping). 2 consecutive outputs per block,
// epilogue bias/c_prev prefetch (R16). Fast MUFU epilogue. No .nc/evict/TMA.

#define H 1024
#define D 1024
#define NOUT 512   // blocks; outputs 2*bid and 2*bid+1
#define NLDG 5     // rows 0..4 via LDG, rows 5..7 via cp.async

__device__ __forceinline__ float warp_reduce(float v) {
    #pragma unroll
    for (int off = 16; off > 0; off >>= 1)
        v += __shfl_xor_sync(0xFFFFFFFFu, v, off);
    return v;
}

__device__ __forceinline__ float fast_tanh(float x) {
    float r;
    asm("tanh.approx.f32 %0, %1;" : "=f"(r) : "f"(x));
    return r;
}
__device__ __forceinline__ float fast_sigmoid(float x) {
    return 0.5f * fast_tanh(0.5f * x) + 0.5f;
}

__global__ __launch_bounds__(256)
void lstm_row0_asym_kernel(const float* __restrict__ x,
                           const float* __restrict__ h,
                           const float* __restrict__ c_prev,
                           const float* __restrict__ Wih,
                           const float* __restrict__ Whh,
                           const float* __restrict__ bih,
                           const float* __restrict__ bhh,
                           float* __restrict__ out) {
    // async path: 3 rows x 2 outputs x 256 float4 = 24KB
    __shared__ __align__(128) float4 swh[3][2][256];
    __shared__ float sums[2][8];

    const int n0   = 2 * blockIdx.x;
    const int tid  = threadIdx.x;
    const int wid  = tid >> 5;            // row index 0..7
    const int lane = tid & 31;
    const int gate = wid >> 1;
    const int mat  = wid & 1;

    // ---- epilogue prefetch: lanes 0,1 of warp 0 pull biases + c_prev early ----
    float pb0 = 0.f, pb1 = 0.f, pb2 = 0.f, pb3 = 0.f;
    float pc0 = 0.f, pc1 = 0.f, pc2 = 0.f, pc3 = 0.f;
    float pcp = 0.f;
    if (tid < 2) {
        const int n = n0 + tid;
        pb0 = bih[n];          pc0 = bhh[n];
        pb1 = bih[H + n];      pc1 = bhh[H + n];
        pb2 = bih[2 * H + n];  pc2 = bhh[2 * H + n];
        pb3 = bih[3 * H + n];  pc3 = bhh[3 * H + n];
        pcp = c_prev[n];
    }

    const float* __restrict__ Wb = (mat ? Whh : Wih) + (size_t)(gate * H + n0) * D;
    const float4* __restrict__ v4 = reinterpret_cast<const float4*>(mat ? h : x);

    float acc0 = 0.0f, acc1 = 0.0f;

    if (wid >= NLDG) {
        // ---- async path: row wid for both outputs (rows 5,6,7) ----
        const int s = wid - NLDG;
        const float* s0 = Wb;
        const float* s1 = Wb + D;                    // adjacent row (n1)
        #pragma unroll
        for (int i = 0; i < 8; i++) {
            const int idx = lane + i * 32;
            uint32_t d0 = (uint32_t)__cvta_generic_to_shared(&swh[s][0][idx]);
            uint32_t d1 = (uint32_t)__cvta_generic_to_shared(&swh[s][1][idx]);
            asm volatile("cp.async.cg.shared.global [%0], [%1], 16;"
                         :: "r"(d0), "l"(s0 + idx * 4) : "memory");
            asm volatile("cp.async.cg.shared.global [%0], [%1], 16;"
                         :: "r"(d1), "l"(s1 + idx * 4) : "memory");
        }
        asm volatile("cp.async.commit_group;" ::: "memory");

        // Vector (L1/L2-hot) overlaps the async transfers.
        float4 vr[8];
        #pragma unroll
        for (int i = 0; i < 8; i++)
            vr[i] = v4[lane + i * 32];

        asm volatile("cp.async.wait_group 0;" ::: "memory");
        __syncwarp();

        #pragma unroll
        for (int i = 0; i < 8; i++) {
            const int idx = lane + i * 32;
            const float4 w0 = swh[s][0][idx];
            const float4 w1 = swh[s][1][idx];
            acc0 += w0.x * vr[i].x + w0.y * vr[i].y + w0.z * vr[i].z + w0.w * vr[i].w;
            acc1 += w1.x * vr[i].x + w1.y * vr[i].y + w1.z * vr[i].z + w1.w * vr[i].w;
        }
    } else {
        // ---- LDG path: row wid for both outputs, interleaved, L2-only (.cg) ----
        const float4* __restrict__ wa = reinterpret_cast<const float4*>(Wb);
        const float4* __restrict__ wb = wa + D / 4;  // adjacent row (n1)
        #pragma unroll
        for (int i = 0; i < 8; i++) {
            const int idx = lane + i * 32;
            const float4 w0 = __ldcg(&wa[idx]);
            const float4 w1 = __ldcg(&wb[idx]);
            const float4 xv = v4[idx];
            acc0 += w0.x * xv.x + w0.y * xv.y + w0.z * xv.z + w0.w * xv.w;
            acc1 += w1.x * xv.x + w1.y * xv.y + w1.z * xv.z + w1.w * xv.w;
        }
    }

    acc0 = warp_reduce(acc0);
    acc1 = warp_reduce(acc1);
    if (lane == 0) {
        sums[0][wid] = acc0;   // row r for output 0
        sums[1][wid] = acc1;   // row r for output 1
    }
    __syncthreads();

    // Two epilogues on two lanes of warp 0; biases/c_prev already in registers.
    // gate g uses rows 2g (Wih·x) and 2g+1 (Whh·h).
    if (tid < 2) {
        const int o = tid;
        const int n = n0 + o;
        float gi = sums[o][0] + sums[o][1] + pb0 + pc0;
        float gf = sums[o][2] + sums[o][3] + pb1 + pc1;
        float gg = sums[o][4] + sums[o][5] + pb2 + pc2;
        float go = sums[o][6] + sums[o][7] + pb3 + pc3;

        float i_t = fast_sigmoid(gi);
        float f_t = fast_sigmoid(gf);
        float g_t = fast_tanh(gg);
        float o_t = fast_sigmoid(go);

        float c_t = f_t * pcp + i_t * g_t;
        out[n] = o_t * fast_tanh(c_t);
    }
}

extern "C" void kernel_launch(void* const* d_in, const int* in_sizes, int n_in,
                              void* d_out, int out_size) {
    const float* x      = (const float*)d_in[0];
    const float* h      = (const float*)d_in[1];
    const float* c_prev = (const float*)d_in[2];
    const float* Wih    = (const float*)d_in[3];
    const float* Whh    = (const float*)d_in[4];
    const float* bih    = (const float*)d_in[5];
    const float* bhh    = (const float*)d_in[6];
    float* out = (float*)d_out;

    lstm_row0_asym_kernel<<<NOUT, 256>>>(x, h, c_prev, Wih, Whh, bih, bhh, out);
}